// round 2
// baseline (speedup 1.0000x reference)
#include <cuda_runtime.h>

// ---------------- problem constants ----------------
#define NMAX   100000
#define EMAX   500000
#define DIM    128          // IN_DIM == OUT_DIM
#define NHEAD  4
#define HD     32           // head dim

// ---------------- scratch (no allocations allowed) ----------------
__device__ float g_h32[NMAX * HD];     // first 32 cols of h (only cols the scatter needs)
__device__ float g_as[NMAX * NHEAD];   // alpha_src per node
__device__ float g_ad[NMAX * NHEAD];   // alpha_dst per node
__device__ float g_sums[NHEAD];        // softmax denominators
__device__ float g_WT[DIM * DIM];      // W_lin transposed: [k][o]
__device__ int   g_is64;               // edge_index dtype flag

// ---------------- K0: prep (transpose W, zero sums, sniff edge dtype) ----------------
__global__ void prep_kernel(const float* __restrict__ Wlin,
                            const unsigned int* __restrict__ ei_raw) {
    int tid = threadIdx.x;
    for (int i = tid; i < DIM * DIM; i += 256) {
        int o = i >> 7, k = i & 127;
        g_WT[k * DIM + o] = Wlin[o * DIM + k];
    }
    if (tid < NHEAD) g_sums[tid] = 0.0f;
    if (tid == 0) {
        // int64 little-endian indices < 100000 => every odd 32-bit word is 0.
        int all0 = 1;
        for (int i = 0; i < 64; i++)
            if (ei_raw[2 * i + 1] != 0u) { all0 = 0; break; }
        g_is64 = all0;
    }
}

// ---------------- K1: GEMM h = X W^T + b, epilogue computes alphas ----------------
// block: 256 threads, 128x128 output tile, K=128 in one shot.
// smem: Xs [128][129] (row-major, padded), Ws = WT [128][128].
#define XS_STRIDE 129
#define SMEM_BYTES ((128 * XS_STRIDE + 128 * 128) * 4)

__global__ __launch_bounds__(256, 1)
void gemm_kernel(const float* __restrict__ X,
                 const float* __restrict__ blin,
                 const float* __restrict__ Watt,
                 float* __restrict__ out, int N) {
    extern __shared__ float sm[];
    float* Xs = sm;                       // [128][129]
    float* Ws = sm + 128 * XS_STRIDE;     // [k][o] stride 128
    __shared__ float sWa[NHEAD * 2 * DIM];
    __shared__ float sb[DIM];

    int tid = threadIdx.x;
    for (int i = tid; i < NHEAD * 2 * DIM; i += 256) sWa[i] = Watt[i];
    if (tid < DIM) sb[tid] = blin[tid];

    // load transposed W (already [k][o]) — coalesced float4
    {
        const float4* src = (const float4*)g_WT;
        float4* dst = (float4*)Ws;
        for (int i = tid; i < DIM * (DIM / 4); i += 256) dst[i] = src[i];
    }
    // load X tile (row-major, stride 129)
    int row0 = blockIdx.x * 128;
    for (int i = tid; i < 128 * 32; i += 256) {
        int r = i >> 5, k4 = i & 31;
        float4 v = make_float4(0.f, 0.f, 0.f, 0.f);
        if (row0 + r < N) v = ((const float4*)X)[(size_t)(row0 + r) * 32 + k4];
        float* p = &Xs[r * XS_STRIDE + k4 * 4];
        p[0] = v.x; p[1] = v.y; p[2] = v.z; p[3] = v.w;
    }
    __syncthreads();

    int tx = tid & 15, ty = tid >> 4;
    int c = tx * 8;                       // this thread's 8 output columns

    unsigned long long acc[8][4];         // f32x2 pairs: cols (c+2p, c+2p+1)
    #pragma unroll
    for (int r = 0; r < 8; r++)
        #pragma unroll
        for (int p = 0; p < 4; p++) acc[r][p] = 0ull;

    #pragma unroll 4
    for (int k = 0; k < 128; k++) {
        const unsigned long long* bp =
            (const unsigned long long*)&Ws[k * DIM + c];
        unsigned long long b0 = bp[0], b1 = bp[1], b2 = bp[2], b3 = bp[3];
        #pragma unroll
        for (int r = 0; r < 8; r++) {
            float a = Xs[(ty * 8 + r) * XS_STRIDE + k];
            unsigned int au = __float_as_uint(a);
            unsigned long long a2;
            asm("mov.b64 %0, {%1, %1};" : "=l"(a2) : "r"(au));
            asm("fma.rn.f32x2 %0, %1, %2, %0;" : "+l"(acc[r][0]) : "l"(a2), "l"(b0));
            asm("fma.rn.f32x2 %0, %1, %2, %0;" : "+l"(acc[r][1]) : "l"(a2), "l"(b1));
            asm("fma.rn.f32x2 %0, %1, %2, %0;" : "+l"(acc[r][2]) : "l"(a2), "l"(b2));
            asm("fma.rn.f32x2 %0, %1, %2, %0;" : "+l"(acc[r][3]) : "l"(a2), "l"(b3));
        }
    }

    // epilogue: add bias, store h to out (+h term) and g_h32, compute alphas
    float hv[8][8];
    #pragma unroll
    for (int r = 0; r < 8; r++)
        #pragma unroll
        for (int p = 0; p < 4; p++) {
            float lo = __uint_as_float((unsigned)(acc[r][p] & 0xffffffffull));
            float hi = __uint_as_float((unsigned)(acc[r][p] >> 32));
            hv[r][2 * p]     = lo + sb[c + 2 * p];
            hv[r][2 * p + 1] = hi + sb[c + 2 * p + 1];
        }

    #pragma unroll
    for (int r = 0; r < 8; r++) {
        int row = row0 + ty * 8 + r;
        if (row < N) {
            float4 v0 = make_float4(hv[r][0], hv[r][1], hv[r][2], hv[r][3]);
            float4 v1 = make_float4(hv[r][4], hv[r][5], hv[r][6], hv[r][7]);
            ((float4*)out)[(size_t)row * 32 + tx * 2]     = v0;
            ((float4*)out)[(size_t)row * 32 + tx * 2 + 1] = v1;
            if (tx < 4) {   // cols 0..31 feed the messages
                ((float4*)g_h32)[row * 8 + tx * 2]     = v0;
                ((float4*)g_h32)[row * 8 + tx * 2 + 1] = v1;
            }
        }
    }

    // alphas: alpha_src[n,hh] = sum_o h[n,o]*Wa[hh][o]; alpha_dst uses Wa[hh][128+o]
    #pragma unroll
    for (int r = 0; r < 8; r++) {
        int row = row0 + ty * 8 + r;
        float ps[NHEAD], pd[NHEAD];
        #pragma unroll
        for (int hh = 0; hh < NHEAD; hh++) {
            float s1 = 0.f, s2 = 0.f;
            #pragma unroll
            for (int j = 0; j < 8; j++) {
                s1 += hv[r][j] * sWa[hh * 2 * DIM + c + j];
                s2 += hv[r][j] * sWa[hh * 2 * DIM + DIM + c + j];
            }
            #pragma unroll
            for (int off = 8; off; off >>= 1) {
                s1 += __shfl_down_sync(0xffffffffu, s1, off, 16);
                s2 += __shfl_down_sync(0xffffffffu, s2, off, 16);
            }
            ps[hh] = s1; pd[hh] = s2;
        }
        if (tx == 0 && row < N) {
            ((float4*)g_as)[row] = make_float4(ps[0], ps[1], ps[2], ps[3]);
            ((float4*)g_ad)[row] = make_float4(pd[0], pd[1], pd[2], pd[3]);
        }
    }
}

// ---------------- K2: softmax denominators (b_att cancels; no max needed) ----------------
__global__ __launch_bounds__(256)
void sums_kernel(const void* __restrict__ ei, int E) {
    int e = blockIdx.x * 256 + threadIdx.x;
    float v0 = 0.f, v1 = 0.f, v2 = 0.f, v3 = 0.f;
    if (e < E) {
        long long s, d;
        if (g_is64) {
            const long long* p = (const long long*)ei;
            s = p[e]; d = p[E + e];
        } else {
            const int* p = (const int*)ei;
            s = p[e]; d = p[E + e];
        }
        float4 as = ((const float4*)g_as)[s];
        float4 ad = ((const float4*)g_ad)[d];
        v0 = __expf(as.x + ad.x);
        v1 = __expf(as.y + ad.y);
        v2 = __expf(as.z + ad.z);
        v3 = __expf(as.w + ad.w);
    }
    #pragma unroll
    for (int off = 16; off; off >>= 1) {
        v0 += __shfl_xor_sync(0xffffffffu, v0, off);
        v1 += __shfl_xor_sync(0xffffffffu, v1, off);
        v2 += __shfl_xor_sync(0xffffffffu, v2, off);
        v3 += __shfl_xor_sync(0xffffffffu, v3, off);
    }
    __shared__ float ss[NHEAD];
    if (threadIdx.x < NHEAD) ss[threadIdx.x] = 0.f;
    __syncthreads();
    if ((threadIdx.x & 31) == 0) {
        atomicAdd(&ss[0], v0); atomicAdd(&ss[1], v1);
        atomicAdd(&ss[2], v2); atomicAdd(&ss[3], v3);
    }
    __syncthreads();
    if (threadIdx.x < NHEAD) atomicAdd(&g_sums[threadIdx.x], ss[threadIdx.x]);
}

// ---------------- K3: scatter — one warp per edge, vector red.add ----------------
__global__ __launch_bounds__(256)
void scatter_kernel(const void* __restrict__ ei, float* __restrict__ out, int E) {
    int warp = (blockIdx.x * 256 + threadIdx.x) >> 5;
    int lane = threadIdx.x & 31;
    if (warp >= E) return;
    int e = warp;
    long long s, d;
    if (g_is64) {
        const long long* p = (const long long*)ei;
        s = p[e]; d = p[E + e];
    } else {
        const int* p = (const int*)ei;
        s = p[e]; d = p[E + e];
    }
    int hh = lane >> 3;        // head 0..3
    int j  = lane & 7;         // float4 chunk within head-dim 32
    float as = g_as[s * NHEAD + hh];
    float ad = g_ad[d * NHEAD + hh];
    float w  = __fdividef(__expf(as + ad), g_sums[hh]);
    float4 sv = ((const float4*)g_h32)[s * 8 + j];
    float mx = sv.x * w, my = sv.y * w, mz = sv.z * w, mw = sv.w * w;
    float* p = out + (size_t)d * DIM + hh * HD + j * 4;
    asm volatile("red.global.add.v4.f32 [%0], {%1, %2, %3, %4};"
                 :: "l"(p), "f"(mx), "f"(my), "f"(mz), "f"(mw) : "memory");
}

// ---------------- launch ----------------
extern "C" void kernel_launch(void* const* d_in, const int* in_sizes, int n_in,
                              void* d_out, int out_size) {
    const float* X    = (const float*)d_in[0];
    const void*  ei   = d_in[1];
    const float* Wlin = (const float*)d_in[2];
    const float* blin = (const float*)d_in[3];
    const float* Watt = (const float*)d_in[4];
    // d_in[5] = b_att: cancels in the softmax, unused.
    float* out = (float*)d_out;

    int N = in_sizes[0] / DIM;
    int E = in_sizes[1] / 2;

    cudaFuncSetAttribute(gemm_kernel,
                         cudaFuncAttributeMaxDynamicSharedMemorySize, SMEM_BYTES);

    prep_kernel<<<1, 256>>>(Wlin, (const unsigned int*)ei);
    gemm_kernel<<<(N + 127) / 128, 256, SMEM_BYTES>>>(X, blin, Watt, out, N);
    sums_kernel<<<(E + 255) / 256, 256>>>(ei, E);
    {
        long long threads = (long long)E * 32;
        int blocks = (int)((threads + 255) / 256);
        scatter_kernel<<<blocks, 256>>>(ei, out, E);
    }
}

// round 3
// speedup vs baseline: 1.4516x; 1.4516x over previous
#include <cuda_runtime.h>

#define NMAX   100000
#define EMAX   500000
#define DIM    128
#define NHEAD  4
#define HD     32
#define NBLK   391          // ceil(NMAX/256)

// ---------------- scratch ----------------
__device__ float g_h32[NMAX * HD];
__device__ float g_eas[NMAX * NHEAD];   // exp(alpha_src)
__device__ float g_ead[NMAX * NHEAD];   // exp(alpha_dst)
__device__ float g_sums[NHEAD];
__device__ float g_WT[DIM * DIM];       // [k][o]
__device__ int   g_is64;
__device__ int   g_cnt[NMAX];
__device__ int   g_fill[NMAX];
__device__ int   g_intra[NMAX];
__device__ int   g_bsum[512];
__device__ int   g_boff[512];
__device__ int   g_se[EMAX];
__device__ int   g_de[EMAX];
__device__ int   g_esrc[EMAX];

// ---------------- K0: prep ----------------
__global__ void prep_kernel(const float* __restrict__ Wlin,
                            const unsigned int* __restrict__ ei_raw) {
    int tid = blockIdx.x * blockDim.x + threadIdx.x;
    int total = gridDim.x * blockDim.x;
    for (int i = tid; i < NMAX; i += total) { g_cnt[i] = 0; g_fill[i] = 0; }
    for (int i = tid; i < DIM * DIM; i += total) {
        int o = i >> 7, k = i & 127;
        g_WT[k * DIM + o] = Wlin[i];
    }
    if (blockIdx.x == 0) {
        if (threadIdx.x < NHEAD) g_sums[threadIdx.x] = 0.0f;
        if (threadIdx.x == 0) {
            int all0 = 1;
            for (int i = 0; i < 64; i++)
                if (ei_raw[2 * i + 1] != 0u) { all0 = 0; break; }
            g_is64 = all0;
        }
    }
}

// ---------------- K1: GEMM + alpha/exp epilogue ----------------
// smem: Wp u64[128][64] pair-swizzled (64KB) + Xs float[2][32][132] (33.8KB)
#define XCH_STRIDE 132
#define GEMM_SMEM  (16384 * 4 + 2 * 32 * XCH_STRIDE * 4)

__global__ __launch_bounds__(256, 2)
void gemm_kernel(const float* __restrict__ X,
                 const float* __restrict__ blin,
                 const float* __restrict__ Watt,
                 float* __restrict__ out, int N) {
    extern __shared__ float sm[];
    unsigned long long* Wp = (unsigned long long*)sm;   // [k][pos] pos(q)=(q&3)*16+(q>>2)
    float* Xs = sm + 16384;                             // [buf][k][m], stride 132
    __shared__ float sWa[NHEAD * 2 * DIM];
    __shared__ float sb[DIM];

    int tid = threadIdx.x;
    for (int i = tid; i < NHEAD * 2 * DIM; i += 256) sWa[i] = Watt[i];
    if (tid < DIM) sb[tid] = blin[tid];

    // W: g_WT [k][o] -> pair-swizzled u64 layout (conflict-free b reads)
    for (int i = tid; i < DIM * 32; i += 256) {
        int k = i >> 5, cq = i & 31;
        float4 w4 = ((const float4*)g_WT)[i];
        int q0 = 2 * cq, q1 = 2 * cq + 1;
        int pos0 = (q0 & 3) * 16 + (q0 >> 2);
        int pos1 = (q1 & 3) * 16 + (q1 >> 2);
        unsigned long long lo, hi;
        asm("mov.b64 %0, {%1, %2};" : "=l"(lo) : "r"(__float_as_uint(w4.x)), "r"(__float_as_uint(w4.y)));
        asm("mov.b64 %0, {%1, %2};" : "=l"(hi) : "r"(__float_as_uint(w4.z)), "r"(__float_as_uint(w4.w)));
        Wp[k * 64 + pos0] = lo;
        Wp[k * 64 + pos1] = hi;
    }

    int row0 = blockIdx.x * 128;
    float4 xreg[4];

    auto loadX = [&](int ch) {
        #pragma unroll
        for (int t = 0; t < 4; t++) {
            int idx = tid + t * 256;
            int m = idx >> 3, kq = idx & 7;
            xreg[t] = make_float4(0.f, 0.f, 0.f, 0.f);
            if (row0 + m < N)
                xreg[t] = ((const float4*)X)[(size_t)(row0 + m) * 32 + ch * 8 + kq];
        }
    };
    auto storeX = [&](int buf) {
        float* base = &Xs[buf * 32 * XCH_STRIDE];
        #pragma unroll
        for (int t = 0; t < 4; t++) {
            int idx = tid + t * 256;
            int m = idx >> 3, kq = idx & 7;
            base[(kq * 4 + 0) * XCH_STRIDE + m] = xreg[t].x;
            base[(kq * 4 + 1) * XCH_STRIDE + m] = xreg[t].y;
            base[(kq * 4 + 2) * XCH_STRIDE + m] = xreg[t].z;
            base[(kq * 4 + 3) * XCH_STRIDE + m] = xreg[t].w;
        }
    };

    loadX(0); storeX(0);
    __syncthreads();

    int tx = tid & 15, ty = tid >> 4;
    int c = tx * 8;

    unsigned long long acc[8][4];
    #pragma unroll
    for (int r = 0; r < 8; r++)
        #pragma unroll
        for (int p = 0; p < 4; p++) acc[r][p] = 0ull;

    for (int ch = 0; ch < 4; ch++) {
        if (ch < 3) loadX(ch + 1);
        int buf = ch & 1;
        const float* xb = &Xs[buf * 32 * XCH_STRIDE];
        #pragma unroll 8
        for (int k = 0; k < 32; k++) {
            float4 a0 = *(const float4*)&xb[k * XCH_STRIDE + ty * 8];
            float4 a1 = *(const float4*)&xb[k * XCH_STRIDE + ty * 8 + 4];
            unsigned long long arep[8];
            const float* av = &a0.x;
            #pragma unroll
            for (int r = 0; r < 4; r++)
                asm("mov.b64 %0, {%1, %1};" : "=l"(arep[r]) : "r"(__float_as_uint(av[r])));
            const float* av1 = &a1.x;
            #pragma unroll
            for (int r = 0; r < 4; r++)
                asm("mov.b64 %0, {%1, %1};" : "=l"(arep[4 + r]) : "r"(__float_as_uint(av1[r])));
            const unsigned long long* wrow = &Wp[(ch * 32 + k) * 64];
            #pragma unroll
            for (int p = 0; p < 4; p++) {
                unsigned long long b = wrow[p * 16 + tx];
                #pragma unroll
                for (int r = 0; r < 8; r++)
                    asm("fma.rn.f32x2 %0, %1, %2, %0;" : "+l"(acc[r][p]) : "l"(arep[r]), "l"(b));
            }
        }
        if (ch < 3) {
            __syncthreads();
            storeX(buf ^ 1);
            __syncthreads();
        }
    }

    // epilogue
    float hv[8][8];
    #pragma unroll
    for (int r = 0; r < 8; r++)
        #pragma unroll
        for (int p = 0; p < 4; p++) {
            float lo = __uint_as_float((unsigned)(acc[r][p] & 0xffffffffull));
            float hi = __uint_as_float((unsigned)(acc[r][p] >> 32));
            hv[r][2 * p]     = lo + sb[c + 2 * p];
            hv[r][2 * p + 1] = hi + sb[c + 2 * p + 1];
        }

    #pragma unroll
    for (int r = 0; r < 8; r++) {
        int row = row0 + ty * 8 + r;
        if (row < N) {
            float4 v0 = make_float4(hv[r][0], hv[r][1], hv[r][2], hv[r][3]);
            float4 v1 = make_float4(hv[r][4], hv[r][5], hv[r][6], hv[r][7]);
            ((float4*)out)[(size_t)row * 32 + tx * 2]     = v0;
            ((float4*)out)[(size_t)row * 32 + tx * 2 + 1] = v1;
            if (tx < 4) {
                ((float4*)g_h32)[row * 8 + tx * 2]     = v0;
                ((float4*)g_h32)[row * 8 + tx * 2 + 1] = v1;
            }
        }
    }

    #pragma unroll
    for (int r = 0; r < 8; r++) {
        int row = row0 + ty * 8 + r;
        float ps[NHEAD], pd[NHEAD];
        #pragma unroll
        for (int hh = 0; hh < NHEAD; hh++) {
            float s1 = 0.f, s2 = 0.f;
            #pragma unroll
            for (int j = 0; j < 8; j++) {
                s1 += hv[r][j] * sWa[hh * 2 * DIM + c + j];
                s2 += hv[r][j] * sWa[hh * 2 * DIM + DIM + c + j];
            }
            #pragma unroll
            for (int off = 8; off; off >>= 1) {
                s1 += __shfl_down_sync(0xffffffffu, s1, off, 16);
                s2 += __shfl_down_sync(0xffffffffu, s2, off, 16);
            }
            ps[hh] = s1; pd[hh] = s2;
        }
        if (tx == 0 && row < N) {
            ((float4*)g_eas)[row] = make_float4(__expf(ps[0]), __expf(ps[1]), __expf(ps[2]), __expf(ps[3]));
            ((float4*)g_ead)[row] = make_float4(__expf(pd[0]), __expf(pd[1]), __expf(pd[2]), __expf(pd[3]));
        }
    }
}

// ---------------- K2: edge pass — idx decode, histogram, softmax sums ----------------
__global__ __launch_bounds__(256)
void edge_kernel(const void* __restrict__ ei, int E) {
    int e = blockIdx.x * 256 + threadIdx.x;
    float v0 = 0.f, v1 = 0.f, v2 = 0.f, v3 = 0.f;
    if (e < E) {
        int s, d;
        if (g_is64) {
            const long long* p = (const long long*)ei;
            s = (int)p[e]; d = (int)p[E + e];
        } else {
            const int* p = (const int*)ei;
            s = p[e]; d = p[E + e];
        }
        g_se[e] = s; g_de[e] = d;
        atomicAdd(&g_cnt[d], 1);
        float4 as = ((const float4*)g_eas)[s];
        float4 ad = ((const float4*)g_ead)[d];
        v0 = as.x * ad.x; v1 = as.y * ad.y; v2 = as.z * ad.z; v3 = as.w * ad.w;
    }
    #pragma unroll
    for (int off = 16; off; off >>= 1) {
        v0 += __shfl_xor_sync(0xffffffffu, v0, off);
        v1 += __shfl_xor_sync(0xffffffffu, v1, off);
        v2 += __shfl_xor_sync(0xffffffffu, v2, off);
        v3 += __shfl_xor_sync(0xffffffffu, v3, off);
    }
    __shared__ float ss[NHEAD];
    if (threadIdx.x < NHEAD) ss[threadIdx.x] = 0.f;
    __syncthreads();
    if ((threadIdx.x & 31) == 0) {
        atomicAdd(&ss[0], v0); atomicAdd(&ss[1], v1);
        atomicAdd(&ss[2], v2); atomicAdd(&ss[3], v3);
    }
    __syncthreads();
    if (threadIdx.x < NHEAD) atomicAdd(&g_sums[threadIdx.x], ss[threadIdx.x]);
}

// ---------------- K3a: per-block exclusive scan of g_cnt ----------------
__global__ __launch_bounds__(256)
void scanA_kernel() {
    int t = threadIdx.x;
    int i = blockIdx.x * 256 + t;
    int v = (i < NMAX) ? g_cnt[i] : 0;
    int x = v;
    #pragma unroll
    for (int off = 1; off < 32; off <<= 1) {
        int y = __shfl_up_sync(0xffffffffu, x, off);
        if ((t & 31) >= off) x += y;
    }
    __shared__ int wsum[8];
    if ((t & 31) == 31) wsum[t >> 5] = x;
    __syncthreads();
    if (t < 8) {
        int y = wsum[t], z = y;
        #pragma unroll
        for (int off = 1; off < 8; off <<= 1) {
            int q = __shfl_up_sync(0xffu, z, off);
            if (t >= off) z += q;
        }
        wsum[t] = z - y;   // exclusive warp offsets
    }
    __syncthreads();
    int excl = x - v + wsum[t >> 5];
    if (i < NMAX) g_intra[i] = excl;
    if (t == 255) g_bsum[blockIdx.x] = excl + v;
}

// ---------------- K3b: scan of 391 block totals ----------------
__global__ __launch_bounds__(512)
void scanB_kernel() {
    __shared__ int s0[512], s1[512];
    int t = threadIdx.x;
    int v = (t < NBLK) ? g_bsum[t] : 0;
    s0[t] = v;
    __syncthreads();
    int* a = s0; int* b = s1;
    for (int off = 1; off < 512; off <<= 1) {
        int x = a[t];
        if (t >= off) x += a[t - off];
        b[t] = x;
        __syncthreads();
        int* tmp = a; a = b; b = tmp;
    }
    if (t < NBLK) g_boff[t] = a[t] - v;   // exclusive
}

// ---------------- K4: fill CSR (src ids grouped by dst) ----------------
__global__ __launch_bounds__(256)
void fill_kernel(int E) {
    int e = blockIdx.x * 256 + threadIdx.x;
    if (e >= E) return;
    int d = g_de[e];
    int base = g_boff[d >> 8] + g_intra[d] + atomicAdd(&g_fill[d], 1);
    g_esrc[base] = g_se[e];
}

// ---------------- K5: gather — one warp per dst, no atomics ----------------
__global__ __launch_bounds__(256)
void gather_kernel(float* __restrict__ out, int N) {
    int d = (blockIdx.x * 256 + threadIdx.x) >> 5;
    int lane = threadIdx.x & 31;
    if (d >= N) return;
    int base = g_boff[d >> 8] + g_intra[d];
    int n = g_cnt[d];
    float4 fe = ((const float4*)g_ead)[d];
    float4 sm4 = *(const float4*)g_sums;
    float w0 = __fdividef(fe.x, sm4.x);
    float w1 = __fdividef(fe.y, sm4.y);
    float w2 = __fdividef(fe.z, sm4.z);
    float w3 = __fdividef(fe.w, sm4.w);
    float a0 = 0.f, a1 = 0.f, a2 = 0.f, a3 = 0.f;
    for (int i = 0; i < n; i++) {
        int s = g_esrc[base + i];
        float v = g_h32[s * HD + lane];
        float4 ea = ((const float4*)g_eas)[s];
        a0 += v * ea.x; a1 += v * ea.y; a2 += v * ea.z; a3 += v * ea.w;
    }
    float* o = out + (size_t)d * DIM + lane;
    o[0]  += a0 * w0;
    o[32] += a1 * w1;
    o[64] += a2 * w2;
    o[96] += a3 * w3;
}

// ---------------- launch ----------------
extern "C" void kernel_launch(void* const* d_in, const int* in_sizes, int n_in,
                              void* d_out, int out_size) {
    const float* X    = (const float*)d_in[0];
    const void*  ei   = d_in[1];
    const float* Wlin = (const float*)d_in[2];
    const float* blin = (const float*)d_in[3];
    const float* Watt = (const float*)d_in[4];
    float* out = (float*)d_out;

    int N = in_sizes[0] / DIM;
    int E = in_sizes[1] / 2;

    cudaFuncSetAttribute(gemm_kernel,
                         cudaFuncAttributeMaxDynamicSharedMemorySize, GEMM_SMEM);

    prep_kernel<<<200, 512>>>(Wlin, (const unsigned int*)ei);
    gemm_kernel<<<(N + 127) / 128, 256, GEMM_SMEM>>>(X, blin, Watt, out, N);
    edge_kernel<<<(E + 255) / 256, 256>>>(ei, E);
    scanA_kernel<<<NBLK, 256>>>();
    scanB_kernel<<<1, 512>>>();
    fill_kernel<<<(E + 255) / 256, 256>>>(E);
    gather_kernel<<<(N * 32 + 255) / 256, 256>>>(out, N);
}